// round 4
// baseline (speedup 1.0000x reference)
#include <cuda_runtime.h>

#define Bv 16
#define Cv 512
#define Nv 9216
#define Kv 32
#define TN 512

// scratch (no cudaMalloc allowed)
__device__ float g_aw[(size_t)Bv * Nv * Kv];   // 18.9 MB: aw[b][n][k]
__device__ float g_sumaw[Bv * Kv];             // sum over n of aw

typedef unsigned long long u64;

__device__ __forceinline__ u64 pack2(float lo, float hi) {
    u64 r; asm("mov.b64 %0,{%1,%2};" : "=l"(r) : "f"(lo), "f"(hi)); return r;
}
__device__ __forceinline__ void unpack2(u64 v, float& lo, float& hi) {
    asm("mov.b64 {%0,%1},%2;" : "=f"(lo), "=f"(hi) : "l"(v));
}
// packed fp32x2 FMA (FFMA2) — PTX-only, 2x FFMA throughput on sm_103a
__device__ __forceinline__ u64 ffma2(u64 a, u64 b, u64 c) {
    u64 d; asm("fma.rn.f32x2 %0,%1,%2,%3;" : "=l"(d) : "l"(a), "l"(b), "l"(c)); return d;
}

__global__ void k_zero() {
    g_sumaw[threadIdx.x] = 0.0f;
}

// ---------------------------------------------------------------------------
// Kernel 1: per (b, n-tile of 512): compute scaled-L2 logits, softmax over K,
// write aw to scratch, accumulate sum_aw.
// Thread t owns n = n0+2t, n0+2t+1. Accumulators packed by k-pairs (f32x2).
// ---------------------------------------------------------------------------
__global__ void __launch_bounds__(256, 2) k_assign(
    const float* __restrict__ x, const float* __restrict__ cw,
    const float* __restrict__ scale)
{
    extern __shared__ float cwT[];                 // [Cv][Kv] = 64 KB
    __shared__ float s_scale[Kv], s_sc2[Kv], s_saw[Kv];
    const int tid = threadIdx.x;
    const int b   = blockIdx.y;
    const int n0  = blockIdx.x * TN;

    // transpose codewords into smem: cwT[c][k] (conflict-free stores)
    for (int i = tid; i < Cv * Kv; i += 256) {
        int k = i & 31, c = i >> 5;
        cwT[c * Kv + k] = cw[k * Cv + c];
    }
    if (tid < Kv) s_saw[tid] = 0.0f;
    __syncthreads();

    // c2[k] and per-k constants (warp 0)
    if (tid < Kv) {
        float s2 = 0.0f;
        #pragma unroll 8
        for (int c = 0; c < Cv; c++) { float v = cwT[c * Kv + tid]; s2 = fmaf(v, v, s2); }
        float sk = scale[tid];
        s_scale[tid] = sk;
        s_sc2[tid]   = sk * s2;
    }
    __syncthreads();

    const float* xb = x + (size_t)b * Cv * Nv + n0 + 2 * tid;

    u64 acc0[16], acc1[16];
    #pragma unroll
    for (int p = 0; p < 16; p++) { acc0[p] = 0ull; acc1[p] = 0ull; }
    u64 x2p = 0ull;

    // software-pipelined main loop over C
    float2 xv = *reinterpret_cast<const float2*>(xb);
    for (int c = 0; c < Cv; c++) {
        int cn = (c + 1 < Cv) ? c + 1 : Cv - 1;
        float2 xnext = *reinterpret_cast<const float2*>(xb + (size_t)cn * Nv);

        u64 xp = pack2(xv.x, xv.y);
        x2p = ffma2(xp, xp, x2p);                  // x2 for both n's
        u64 d0 = pack2(xv.x, xv.x);
        u64 d1 = pack2(xv.y, xv.y);
        const ulonglong2* row = reinterpret_cast<const ulonglong2*>(cwT + c * Kv);
        #pragma unroll
        for (int q = 0; q < 8; q++) {
            ulonglong2 w = row[q];                 // broadcast LDS.128: cw[c][4q..4q+3]
            acc0[2 * q]     = ffma2(d0, w.x, acc0[2 * q]);
            acc1[2 * q]     = ffma2(d1, w.x, acc1[2 * q]);
            acc0[2 * q + 1] = ffma2(d0, w.y, acc0[2 * q + 1]);
            acc1[2 * q + 1] = ffma2(d1, w.y, acc1[2 * q + 1]);
        }
        xv = xnext;
    }

    float xcA[Kv], xcB[Kv], x2A, x2B;
    #pragma unroll
    for (int p = 0; p < 16; p++) {
        unpack2(acc0[p], xcA[2 * p], xcA[2 * p + 1]);
        unpack2(acc1[p], xcB[2 * p], xcB[2 * p + 1]);
    }
    unpack2(x2p, x2A, x2B);

    float* awout = g_aw + ((size_t)b * Nv + n0 + 2 * tid) * Kv;

    // softmax for n (even) -> aw stored back into xcA
    {
        float l2[Kv];
        float m = -1e30f;
        #pragma unroll
        for (int k = 0; k < Kv; k++) {
            float v = fmaf(s_scale[k], x2A - 2.0f * xcA[k], s_sc2[k]);
            l2[k] = v; m = fmaxf(m, v);
        }
        float s = 0.0f;
        #pragma unroll
        for (int k = 0; k < Kv; k++) { float e = __expf(l2[k] - m); l2[k] = e; s += e; }
        float r = 1.0f / s;
        #pragma unroll
        for (int k = 0; k < Kv; k++) xcA[k] = l2[k] * r;
        #pragma unroll
        for (int q = 0; q < 8; q++)
            reinterpret_cast<float4*>(awout)[q] =
                make_float4(xcA[4 * q], xcA[4 * q + 1], xcA[4 * q + 2], xcA[4 * q + 3]);
    }
    // softmax for n+1 (odd) -> aw stored back into xcB
    {
        float l2[Kv];
        float m = -1e30f;
        #pragma unroll
        for (int k = 0; k < Kv; k++) {
            float v = fmaf(s_scale[k], x2B - 2.0f * xcB[k], s_sc2[k]);
            l2[k] = v; m = fmaxf(m, v);
        }
        float s = 0.0f;
        #pragma unroll
        for (int k = 0; k < Kv; k++) { float e = __expf(l2[k] - m); l2[k] = e; s += e; }
        float r = 1.0f / s;
        #pragma unroll
        for (int k = 0; k < Kv; k++) xcB[k] = l2[k] * r;
        #pragma unroll
        for (int q = 0; q < 8; q++)
            reinterpret_cast<float4*>(awout + Kv)[q] =
                make_float4(xcB[4 * q], xcB[4 * q + 1], xcB[4 * q + 2], xcB[4 * q + 3]);
    }

    // block-level sum_aw (fire-and-forget shared atomics, overlap with other warps)
    #pragma unroll
    for (int k = 0; k < Kv; k++) atomicAdd(&s_saw[k], xcA[k] + xcB[k]);
    __syncthreads();
    if (tid < Kv) atomicAdd(&g_sumaw[b * Kv + tid], s_saw[tid]);
}

// ---------------------------------------------------------------------------
// Kernel 2: enc[b][k][c] = sum_n aw[n][k]*x[c][n] - sum_aw[b][k]*cw[k][c]
// Block = (b, 32 c's). 8 warps split N. Lane <-> c; k-pairs packed f32x2.
// Per-warp smem staging: x chunk transposed (pitch 33, conflict-free) + aw chunk.
// ---------------------------------------------------------------------------
__global__ void __launch_bounds__(256) k_agg(
    const float* __restrict__ x, const float* __restrict__ cw,
    float* __restrict__ out)
{
    extern __shared__ float sm[];   // per-warp: xs[32][33] ; aws[32][32] ; reused for reduction
    const int tid = threadIdx.x, w = tid >> 5, l = tid & 31;
    const int b  = blockIdx.y;
    const int cb = blockIdx.x * 32;
    float* xs  = sm + w * (32 * 33);
    float* aws = sm + 8 * (32 * 33) + w * (32 * 32);

    u64 acc[16];
    #pragma unroll
    for (int p = 0; p < 16; p++) acc[p] = 0ull;

    const float* xb  = x + ((size_t)b * Cv + cb) * Nv;
    const float* awb = g_aw + (size_t)b * Nv * Kv;
    const int nBeg = w * (Nv / 8);

    for (int n0 = nBeg; n0 < nBeg + Nv / 8; n0 += 32) {
        // stage x[cb..cb+32)[n0..n0+32) transposed (coalesced loads, conflict-free stores)
        #pragma unroll 8
        for (int c = 0; c < 32; c++)
            xs[c * 33 + l] = xb[(size_t)c * Nv + n0 + l];
        // stage aw rows (coalesced)
        #pragma unroll 8
        for (int j = 0; j < 32; j++)
            aws[j * 32 + l] = awb[(size_t)(n0 + j) * Kv + l];
        __syncwarp();

        #pragma unroll 4
        for (int j = 0; j < 32; j++) {
            float xv = xs[l * 33 + j];             // lane<->c, stride 33: conflict-free
            u64 xp = pack2(xv, xv);
            const ulonglong2* row = reinterpret_cast<const ulonglong2*>(aws + j * 32);
            #pragma unroll
            for (int q = 0; q < 8; q++) {
                ulonglong2 a2 = row[q];            // broadcast LDS.128
                acc[2 * q]     = ffma2(xp, a2.x, acc[2 * q]);
                acc[2 * q + 1] = ffma2(xp, a2.y, acc[2 * q + 1]);
            }
        }
        __syncwarp();
    }

    // cross-warp reduction + fused epilogue
    __syncthreads();
    u64* red = reinterpret_cast<u64*>(sm);         // [w][p][l] : 32 KB, reuses staging smem
    #pragma unroll
    for (int p = 0; p < 16; p++) red[(w * 16 + p) * 32 + l] = acc[p];
    __syncthreads();

    #pragma unroll
    for (int pp = 0; pp < 2; pp++) {
        int p = 2 * w + pp;
        float v0 = 0.0f, v1 = 0.0f;
        #pragma unroll
        for (int ww = 0; ww < 8; ww++) {
            float a, bb; unpack2(red[(ww * 16 + p) * 32 + l], a, bb);
            v0 += a; v1 += bb;
        }
        int k0 = 2 * p;
        int c  = cb + l;
        float s0 = g_sumaw[b * Kv + k0], s1 = g_sumaw[b * Kv + k0 + 1];
        out[((size_t)b * Kv + k0) * Cv + c]     = v0 - s0 * cw[k0 * Cv + c];
        out[((size_t)b * Kv + k0 + 1) * Cv + c] = v1 - s1 * cw[(k0 + 1) * Cv + c];
    }
}

extern "C" void kernel_launch(void* const* d_in, const int* in_sizes, int n_in,
                              void* d_out, int out_size)
{
    const float* x  = (const float*)d_in[0];   // (B, C, H, W)
    const float* cw = (const float*)d_in[1];   // (K, C)
    const float* sc = (const float*)d_in[2];   // (K,)
    float* out = (float*)d_out;                // (B, K, C)

    // opt-in >48KB dynamic smem (attribute set is not a stream op; capture-safe)
    cudaFuncSetAttribute(k_assign, cudaFuncAttributeMaxDynamicSharedMemorySize, Cv * Kv * 4);
    cudaFuncSetAttribute(k_agg,    cudaFuncAttributeMaxDynamicSharedMemorySize,
                         (8 * 32 * 33 + 8 * 32 * 32) * 4);

    k_zero<<<1, Bv * Kv>>>();
    k_assign<<<dim3(Nv / TN, Bv), 256, Cv * Kv * 4>>>(x, cw, sc);
    k_agg<<<dim3(Cv / 32, Bv), 256, (8 * 32 * 33 + 8 * 32 * 32) * 4>>>(x, cw, out);
}